// round 2
// baseline (speedup 1.0000x reference)
#include <cuda_runtime.h>
#include <math.h>

#define NN 50000
#define EE 800000
#define FF 128
#define HH 128
#define HID2 64
#define TT 8
#define GG 64

// ---------------- scratch (device globals; no allocations allowed) ----------
__device__ __align__(16) float g_deg[NN];        // degree incl. self-loop
__device__ __align__(16) float g_dinv[NN];       // deg^-1/2
__device__ __align__(16) float g_g[NN * HH];     // g = (x@W) * dinv[row]
__device__ __align__(16) float g_acc[NN * HH];   // accumulator (init = g -> self loop)
__device__ __align__(16) float g_sums[GG * HH];  // pooled sums per graph
__device__ __align__(16) float g_cnts[GG];       // node counts per graph

// ---------------- init: deg=1 (self loop), zero pool accumulators -----------
__global__ void k_init(int n) {
    int i = blockIdx.x * blockDim.x + threadIdx.x;
    if (i < n) g_deg[i] = 1.0f;
    if (i < GG * HH) g_sums[i] = 0.0f;
    if (i < GG) g_cnts[i] = 0.0f;
}

// ---------------- degree count over edge destinations -----------------------
__global__ void k_degcount(const int* __restrict__ dst, int e) {
    int i = blockIdx.x * blockDim.x + threadIdx.x;
    if (i < e) atomicAdd(&g_deg[dst[i]], 1.0f);
}

__global__ void k_dinv(int n) {
    int i = blockIdx.x * blockDim.x + threadIdx.x;
    if (i < n) g_dinv[i] = rsqrtf(g_deg[i]);
}

// ---------------- GEMM: g = (x @ W) * dinv[row]; acc = g (self loop) --------
// 64 rows x 128 cols per block, 256 threads, 8x4 register tile per thread.
__global__ __launch_bounds__(256) void k_gemm(const float* __restrict__ x,
                                              const float* __restrict__ W,
                                              int n) {
    __shared__ float Ws[16][HH];   // 8 KB: 16 k-rows of W
    __shared__ float Xs[64][16];   // 4 KB: 64 rows x 16 k

    const int tid  = threadIdx.x;
    const int row0 = blockIdx.x * 64;
    const int cg   = tid & 31;     // column group -> cols cg*4 .. cg*4+3
    const int rg   = tid >> 5;     // row group    -> rows rg*8 .. rg*8+7

    float acc[8][4];
#pragma unroll
    for (int r = 0; r < 8; r++)
#pragma unroll
        for (int c = 0; c < 4; c++) acc[r][c] = 0.0f;

    const int xr = tid >> 2;       // 0..63 row within tile
    const int xq = tid & 3;        // 0..3  float4 within 16-k chunk

    for (int kt = 0; kt < FF; kt += 16) {
        // stage X tile (one float4 per thread, contiguous -> conflict free)
        float4 xv4 = make_float4(0.f, 0.f, 0.f, 0.f);
        int grow = row0 + xr;
        if (grow < n)
            xv4 = *(const float4*)(x + (size_t)grow * FF + kt + xq * 4);
        *(float4*)&Xs[xr][xq * 4] = xv4;

        // stage W tile: 512 float4s, 2 per thread, contiguous
#pragma unroll
        for (int i = 0; i < 2; i++) {
            int f4 = tid * 2 + i;          // 0..511
            int kk = f4 >> 5;              // 0..15
            int j4 = f4 & 31;              // 0..31
            *(float4*)&Ws[kk][j4 * 4] =
                *(const float4*)(W + (size_t)(kt + kk) * HH + j4 * 4);
        }
        __syncthreads();

#pragma unroll
        for (int kk = 0; kk < 16; kk++) {
            float4 w = *(float4*)&Ws[kk][cg * 4];
#pragma unroll
            for (int r = 0; r < 8; r++) {
                float xv = Xs[rg * 8 + r][kk];   // warp broadcast
                acc[r][0] += xv * w.x;
                acc[r][1] += xv * w.y;
                acc[r][2] += xv * w.z;
                acc[r][3] += xv * w.w;
            }
        }
        __syncthreads();
    }

#pragma unroll
    for (int r = 0; r < 8; r++) {
        int row = row0 + rg * 8 + r;
        if (row < n) {
            float s = g_dinv[row];
            float4 v = make_float4(acc[r][0] * s, acc[r][1] * s,
                                   acc[r][2] * s, acc[r][3] * s);
            *(float4*)(g_g   + (size_t)row * HH + cg * 4) = v;
            *(float4*)(g_acc + (size_t)row * HH + cg * 4) = v;  // self-loop term
        }
    }
}

// ---------------- edge scatter: acc[dst] += g[src], one warp per edge -------
// One red.global.add.v4.f32 per lane: 32 lanes x 4 floats = full 128-col row.
__global__ __launch_bounds__(256) void k_scatter(const int* __restrict__ src,
                                                 const int* __restrict__ dst,
                                                 int e) {
    int gt   = blockIdx.x * blockDim.x + threadIdx.x;
    int wid  = gt >> 5;
    int lane = gt & 31;
    if (wid >= e) return;
    int s = __ldg(&src[wid]);
    int d = __ldg(&dst[wid]);
    const float4 v = __ldg((const float4*)(g_g + (size_t)s * HH + lane * 4));
    float* ap = g_acc + (size_t)d * HH + lane * 4;
    asm volatile("red.global.add.v4.f32 [%0], {%1, %2, %3, %4};"
                 :: "l"(ap), "f"(v.x), "f"(v.y), "f"(v.z), "f"(v.w)
                 : "memory");
}

// ---------------- finish GCN (scale+bias+relu) + mean-pool (batch sorted) ---
#define RPB 128
__global__ __launch_bounds__(128) void k_pool(const int* __restrict__ batch,
                                              const float* __restrict__ b,
                                              int n) {
    const int j  = threadIdx.x;
    const int r0 = blockIdx.x * RPB;
    const float bj = b[j];

    float run = 0.0f;
    int   cur = -1;
    int   cl  = 0;
    for (int r = 0; r < RPB; r++) {
        int row = r0 + r;
        if (row >= n) break;
        int bid = batch[row];
        if (bid != cur) {
            if (cur >= 0) {
                atomicAdd(&g_sums[cur * HH + j], run);
                if (j == 0) atomicAdd(&g_cnts[cur], (float)cl);
            }
            cur = bid; run = 0.0f; cl = 0;
        }
        float v = fmaxf(g_acc[(size_t)row * HH + j] * g_dinv[row] + bj, 0.0f);
        run += v;
        cl++;
    }
    if (cur >= 0) {
        atomicAdd(&g_sums[cur * HH + j], run);
        if (j == 0) atomicAdd(&g_cnts[cur], (float)cl);
    }
}

// ---------------- head: fc1+relu, actor softmax, critic ---------------------
__global__ __launch_bounds__(128) void k_head(const float* __restrict__ fc1_w,
                                              const float* __restrict__ fc1_b,
                                              const float* __restrict__ aw,
                                              const float* __restrict__ ab,
                                              const float* __restrict__ cw,
                                              const float* __restrict__ cb,
                                              float* __restrict__ out) {
    const int g = blockIdx.x;
    const int t = threadIdx.x;
    __shared__ float st[HH];
    __shared__ float z[HID2];
    __shared__ float lg[TT];

    st[t] = g_sums[g * HH + t] / fmaxf(g_cnts[g], 1.0f);
    __syncthreads();

    if (t < HID2) {
        float a = fc1_b[t];
#pragma unroll 8
        for (int k = 0; k < HH; k++) a += st[k] * fc1_w[k * HID2 + t];
        z[t] = fmaxf(a, 0.0f);
    }
    __syncthreads();

    if (t < TT) {
        float a = ab[t];
#pragma unroll 8
        for (int k = 0; k < HID2; k++) a += z[k] * aw[k * TT + t];
        lg[t] = a;
    }
    if (t == 32) {  // different warp, runs concurrently with logits
        float v = cb[0];
#pragma unroll 8
        for (int k = 0; k < HID2; k++) v += z[k] * cw[k];
        out[GG * TT + g] = v;
    }
    __syncthreads();

    if (t == 0) {
        float m = -1e30f;
#pragma unroll
        for (int i = 0; i < TT; i++) m = fmaxf(m, lg[i]);
        float ex[TT];
        float s = 0.0f;
#pragma unroll
        for (int i = 0; i < TT; i++) { ex[i] = __expf(lg[i] - m); s += ex[i]; }
        float inv = 1.0f / s;
#pragma unroll
        for (int i = 0; i < TT; i++) out[g * TT + i] = ex[i] * inv;
    }
}

// ---------------- launcher ---------------------------------------------------
extern "C" void kernel_launch(void* const* d_in, const int* in_sizes, int n_in,
                              void* d_out, int out_size) {
    const float* x     = (const float*)d_in[0];
    const int*   eidx  = (const int*)d_in[1];
    const int*   batch = (const int*)d_in[2];
    const float* W     = (const float*)d_in[3];
    const float* b     = (const float*)d_in[4];
    const float* fc1_w = (const float*)d_in[5];
    const float* fc1_b = (const float*)d_in[6];
    const float* aw    = (const float*)d_in[7];
    const float* ab    = (const float*)d_in[8];
    const float* cw    = (const float*)d_in[9];
    const float* cb    = (const float*)d_in[10];
    float* out = (float*)d_out;

    const int n = in_sizes[0] / FF;   // 50000
    const int e = in_sizes[1] / 2;    // 800000
    const int* src = eidx;
    const int* dst = eidx + e;

    k_init<<<(n + 255) / 256, 256>>>(n);
    k_degcount<<<(e + 255) / 256, 256>>>(dst, e);
    k_dinv<<<(n + 255) / 256, 256>>>(n);
    k_gemm<<<(n + 63) / 64, 256>>>(x, W, n);
    {
        long long threads = (long long)e * 32;
        int blocks = (int)((threads + 255) / 256);
        k_scatter<<<blocks, 256>>>(src, dst, e);
    }
    k_pool<<<(n + RPB - 1) / RPB, 128>>>(batch, b, n);
    k_head<<<GG, 128>>>(fc1_w, fc1_b, aw, ab, cw, cb, out);
}

// round 6
// speedup vs baseline: 1.1727x; 1.1727x over previous
#include <cuda_runtime.h>
#include <math.h>

#define NN 50000
#define EE 800000
#define FF 128
#define HH 128
#define HID2 64
#define TT 8
#define GG 64

// ---------------- scratch (device globals; no allocations allowed) ----------
__device__ __align__(16) int   g_cnt[NN];        // in-degree (excl self-loop)
__device__ __align__(16) int   g_base[NN];       // CSR row start
__device__ __align__(16) int   g_cur[NN];        // fill cursor
__device__ __align__(16) int   g_es[EE];         // edge sources grouped by dst
__device__ __align__(16) int   g_bsum[256];      // scan partials
__device__ __align__(16) int   g_boff[256];      // scan block offsets
__device__ __align__(16) float g_dinv[NN];       // (deg+1)^-1/2
__device__ __align__(16) float g_g[NN * HH];     // g = (x@W) * dinv[row]
__device__ __align__(16) float g_h[NN * HH];     // relu'd GCN output
__device__ __align__(16) float g_sums[GG * HH];  // pooled sums per graph
__device__ __align__(16) float g_cnts[GG];       // node counts per graph

// ---------------- zero counters ---------------------------------------------
__global__ void k_zero(int n) {
    int i = blockIdx.x * blockDim.x + threadIdx.x;
    if (i < n) g_cnt[i] = 0;
    if (i < GG * HH) g_sums[i] = 0.0f;
    if (i < GG) g_cnts[i] = 0.0f;
}

// ---------------- in-degree histogram over destinations ---------------------
__global__ void k_count(const int* __restrict__ dst, int e) {
    int i = blockIdx.x * blockDim.x + threadIdx.x;
    if (i < e) atomicAdd(&g_cnt[__ldg(&dst[i])], 1);
}

// ---------------- two-level exclusive scan ----------------------------------
__global__ void k_scan1(int n) {
    __shared__ int sh[256];
    const int t = threadIdx.x;
    const int i = blockIdx.x * 256 + t;
    int v = (i < n) ? g_cnt[i] : 0;
    sh[t] = v;
    __syncthreads();
#pragma unroll
    for (int off = 1; off < 256; off <<= 1) {
        int add = (t >= off) ? sh[t - off] : 0;
        __syncthreads();
        sh[t] += add;
        __syncthreads();
    }
    if (i < n) g_base[i] = sh[t] - v;      // exclusive within block
    if (t == 255) g_bsum[blockIdx.x] = sh[255];
}

__global__ void k_scan2(int nb) {
    __shared__ int sh[256];
    const int t = threadIdx.x;
    int v = (t < nb) ? g_bsum[t] : 0;
    sh[t] = v;
    __syncthreads();
#pragma unroll
    for (int off = 1; off < 256; off <<= 1) {
        int add = (t >= off) ? sh[t - off] : 0;
        __syncthreads();
        sh[t] += add;
        __syncthreads();
    }
    if (t < nb) g_boff[t] = sh[t] - v;
}

__global__ void k_scan3(int n) {
    int i = blockIdx.x * blockDim.x + threadIdx.x;
    if (i < n) {
        int b = g_base[i] + g_boff[i >> 8];
        g_base[i] = b;
        g_cur[i]  = b;
        g_dinv[i] = rsqrtf((float)g_cnt[i] + 1.0f);   // +1 self-loop
    }
}

// ---------------- fill CSR edge array ----------------------------------------
__global__ void k_fill(const int* __restrict__ src, const int* __restrict__ dst, int e) {
    int i = blockIdx.x * blockDim.x + threadIdx.x;
    if (i < e) {
        int d = __ldg(&dst[i]);
        int pos = atomicAdd(&g_cur[d], 1);
        g_es[pos] = __ldg(&src[i]);
    }
}

// ---------------- GEMM: g = (x @ W) * dinv[row] ------------------------------
// 64 rows x 128 cols per block, 256 threads, 8x4 register tile, K-chunk 32.
__global__ __launch_bounds__(256) void k_gemm(const float* __restrict__ x,
                                              const float* __restrict__ W,
                                              int n) {
    __shared__ float Ws[32][HH];   // 16 KB
    __shared__ float Xs[64][32];   // 8 KB

    const int tid  = threadIdx.x;
    const int row0 = blockIdx.x * 64;
    const int cg   = tid & 31;     // cols cg*4 .. cg*4+3
    const int rg   = tid >> 5;     // rows rg*8 .. rg*8+7

    float acc[8][4];
#pragma unroll
    for (int r = 0; r < 8; r++)
#pragma unroll
        for (int c = 0; c < 4; c++) acc[r][c] = 0.0f;

    for (int kt = 0; kt < FF; kt += 32) {
        // stage X tile: 512 float4, 2 per thread
#pragma unroll
        for (int i = 0; i < 2; i++) {
            int f4 = tid + i * 256;
            int xr = f4 >> 3;            // 0..63
            int xq = f4 & 7;             // 0..7
            float4 v = make_float4(0.f, 0.f, 0.f, 0.f);
            int grow = row0 + xr;
            if (grow < n)
                v = *(const float4*)(x + (size_t)grow * FF + kt + xq * 4);
            *(float4*)&Xs[xr][xq * 4] = v;
        }
        // stage W tile: 1024 float4, 4 per thread
#pragma unroll
        for (int i = 0; i < 4; i++) {
            int f4 = tid + i * 256;
            int kk = f4 >> 5;            // 0..31
            int j4 = f4 & 31;            // 0..31
            *(float4*)&Ws[kk][j4 * 4] =
                *(const float4*)(W + (size_t)(kt + kk) * HH + j4 * 4);
        }
        __syncthreads();

#pragma unroll
        for (int kk = 0; kk < 32; kk++) {
            float4 w = *(float4*)&Ws[kk][cg * 4];
#pragma unroll
            for (int r = 0; r < 8; r++) {
                float xv = Xs[rg * 8 + r][kk];   // warp-uniform broadcast
                acc[r][0] += xv * w.x;
                acc[r][1] += xv * w.y;
                acc[r][2] += xv * w.z;
                acc[r][3] += xv * w.w;
            }
        }
        __syncthreads();
    }

#pragma unroll
    for (int r = 0; r < 8; r++) {
        int row = row0 + rg * 8 + r;
        if (row < n) {
            float s = g_dinv[row];
            float4 v = make_float4(acc[r][0] * s, acc[r][1] * s,
                                   acc[r][2] * s, acc[r][3] * s);
            *(float4*)(g_g + (size_t)row * HH + cg * 4) = v;
        }
    }
}

// ---------------- CSR gather + fused epilogue --------------------------------
// One warp per dst node; lane handles 4 cols. h = relu(dinv*(g_self + sum) + b)
// 8-edge unroll: 8 independent index loads then 8 independent row loads (MLP=8).
__global__ __launch_bounds__(256) void k_gather(const float* __restrict__ bias) {
    const int wid  = (blockIdx.x * 256 + threadIdx.x) >> 5;
    const int lane = threadIdx.x & 31;
    if (wid >= NN) return;

    const float4* __restrict__ gp = (const float4*)g_g;
    float4 acc = __ldg(gp + (size_t)wid * 32 + lane);   // self-loop term

    const int b0  = g_base[wid];
    const int end = b0 + g_cnt[wid];
    int k = b0;
    for (; k + 8 <= end; k += 8) {
        int s[8];
#pragma unroll
        for (int u = 0; u < 8; u++) s[u] = __ldg(&g_es[k + u]);
        float4 a[8];
#pragma unroll
        for (int u = 0; u < 8; u++) a[u] = __ldg(gp + (size_t)s[u] * 32 + lane);
        float4 p0, p1;
        p0.x = (a[0].x + a[1].x) + (a[2].x + a[3].x);
        p0.y = (a[0].y + a[1].y) + (a[2].y + a[3].y);
        p0.z = (a[0].z + a[1].z) + (a[2].z + a[3].z);
        p0.w = (a[0].w + a[1].w) + (a[2].w + a[3].w);
        p1.x = (a[4].x + a[5].x) + (a[6].x + a[7].x);
        p1.y = (a[4].y + a[5].y) + (a[6].y + a[7].y);
        p1.z = (a[4].z + a[5].z) + (a[6].z + a[7].z);
        p1.w = (a[4].w + a[5].w) + (a[6].w + a[7].w);
        acc.x += p0.x + p1.x;
        acc.y += p0.y + p1.y;
        acc.z += p0.z + p1.z;
        acc.w += p0.w + p1.w;
    }
    for (; k < end; k++) {
        int s = __ldg(&g_es[k]);
        float4 a = __ldg(gp + (size_t)s * 32 + lane);
        acc.x += a.x; acc.y += a.y; acc.z += a.z; acc.w += a.w;
    }

    const float dv = g_dinv[wid];
    const float4 bb = __ldg((const float4*)bias + lane);
    float4 h;
    h.x = fmaxf(acc.x * dv + bb.x, 0.0f);
    h.y = fmaxf(acc.y * dv + bb.y, 0.0f);
    h.z = fmaxf(acc.z * dv + bb.z, 0.0f);
    h.w = fmaxf(acc.w * dv + bb.w, 0.0f);
    ((float4*)g_h)[(size_t)wid * 32 + lane] = h;
}

// ---------------- mean-pool (batch sorted): running-sum flush ----------------
#define RPB 128
__global__ __launch_bounds__(128) void k_pool(const int* __restrict__ batch, int n) {
    const int j  = threadIdx.x;
    const int r0 = blockIdx.x * RPB;

    float run = 0.0f;
    int   cur = -1;
    int   cl  = 0;
    for (int r = 0; r < RPB; r++) {
        int row = r0 + r;
        if (row >= n) break;
        int bid = batch[row];
        if (bid != cur) {
            if (cur >= 0) {
                atomicAdd(&g_sums[cur * HH + j], run);
                if (j == 0) atomicAdd(&g_cnts[cur], (float)cl);
            }
            cur = bid; run = 0.0f; cl = 0;
        }
        run += g_h[(size_t)row * HH + j];
        cl++;
    }
    if (cur >= 0) {
        atomicAdd(&g_sums[cur * HH + j], run);
        if (j == 0) atomicAdd(&g_cnts[cur], (float)cl);
    }
}

// ---------------- head: fc1+relu, actor softmax, critic ----------------------
__global__ __launch_bounds__(128) void k_head(const float* __restrict__ fc1_w,
                                              const float* __restrict__ fc1_b,
                                              const float* __restrict__ aw,
                                              const float* __restrict__ ab,
                                              const float* __restrict__ cw,
                                              const float* __restrict__ cb,
                                              float* __restrict__ out) {
    const int g = blockIdx.x;
    const int t = threadIdx.x;
    __shared__ float st[HH];
    __shared__ float z[HID2];
    __shared__ float lg[TT];

    st[t] = g_sums[g * HH + t] / fmaxf(g_cnts[g], 1.0f);
    __syncthreads();

    if (t < HID2) {
        float a = fc1_b[t];
#pragma unroll 8
        for (int k = 0; k < HH; k++) a += st[k] * fc1_w[k * HID2 + t];
        z[t] = fmaxf(a, 0.0f);
    }
    __syncthreads();

    if (t < TT) {
        float a = ab[t];
#pragma unroll 8
        for (int k = 0; k < HID2; k++) a += z[k] * aw[k * TT + t];
        lg[t] = a;
    }
    if (t == 32) {
        float v = cb[0];
#pragma unroll 8
        for (int k = 0; k < HID2; k++) v += z[k] * cw[k];
        out[GG * TT + g] = v;
    }
    __syncthreads();

    if (t == 0) {
        float m = -1e30f;
#pragma unroll
        for (int i = 0; i < TT; i++) m = fmaxf(m, lg[i]);
        float ex[TT];
        float s = 0.0f;
#pragma unroll
        for (int i = 0; i < TT; i++) { ex[i] = __expf(lg[i] - m); s += ex[i]; }
        float inv = 1.0f / s;
#pragma unroll
        for (int i = 0; i < TT; i++) out[g * TT + i] = ex[i] * inv;
    }
}

// ---------------- launcher ----------------------------------------------------
extern "C" void kernel_launch(void* const* d_in, const int* in_sizes, int n_in,
                              void* d_out, int out_size) {
    const float* x     = (const float*)d_in[0];
    const int*   eidx  = (const int*)d_in[1];
    const int*   batch = (const int*)d_in[2];
    const float* W     = (const float*)d_in[3];
    const float* b     = (const float*)d_in[4];
    const float* fc1_w = (const float*)d_in[5];
    const float* fc1_b = (const float*)d_in[6];
    const float* aw    = (const float*)d_in[7];
    const float* ab    = (const float*)d_in[8];
    const float* cw    = (const float*)d_in[9];
    const float* cb    = (const float*)d_in[10];
    float* out = (float*)d_out;

    const int n = in_sizes[0] / FF;   // 50000
    const int e = in_sizes[1] / 2;    // 800000
    const int* src = eidx;
    const int* dst = eidx + e;
    const int nb = (n + 255) / 256;   // scan blocks (196 <= 256)

    k_zero<<<(n + 255) / 256, 256>>>(n);
    k_count<<<(e + 255) / 256, 256>>>(dst, e);
    k_scan1<<<nb, 256>>>(n);
    k_scan2<<<1, 256>>>(nb);
    k_scan3<<<(n + 255) / 256, 256>>>(n);
    k_fill<<<(e + 255) / 256, 256>>>(src, dst, e);
    k_gemm<<<(n + 63) / 64, 256>>>(x, W, n);
    k_gather<<<(NN * 32 + 255) / 256, 256>>>(b);
    k_pool<<<(n + RPB - 1) / RPB, 128>>>(batch, n);
    k_head<<<GG, 128>>>(fc1_w, fc1_b, aw, ab, cw, cb, out);
}